// round 15
// baseline (speedup 1.0000x reference)
#include <cuda_runtime.h>
#include <cuda_bf16.h>
#include <cstdint>

// Shapes (fixed by the problem)
#define BB      8
#define TIMES   288
#define NNODES  207
#define DD      64
#define TT      288
#define NBT     (BB * TIMES)      // 2304 (b,t) rows
#define NV      (NNODES * DD / 4) // 3312 float4 per row
#define REM4    (NV - 12 * 256)   // 240-thread remainder

// R15: fastest-kernel structure (R8: plain STG.128, one row/block, 256 thr)
// + full store unroll (R14 mechanism): 3312 = 12*256 + 240 -> each thread
// issues 12 unconditional + 1 predicated 128-bit stores back-to-back. Zero
// loop overhead, maximal store MLP. The dur-kernel gap is run-state noise;
// minimizing kernel time maximizes expected dur.
__global__ __launch_bounds__(256, 8)
void tememb_kernel(const int*   __restrict__ TE,
                   const float* __restrict__ W1,
                   const float* __restrict__ b1,
                   const float* __restrict__ W2,
                   const float* __restrict__ b2,
                   float*       __restrict__ out)
{
    const int bt  = blockIdx.x;     // 0 .. 2303
    const int tid = threadIdx.x;    // 0 .. 255

    __shared__ float h[DD];
    __shared__ float o[DD];

    // TE is (B, TIMES, N, 2); only node 0 matters (reference slices [:, :, 0, :]).
    const int* te = TE + (size_t)bt * (NNODES * 2);

    if (tid < DD) {
        int dow = te[0] % 7;  if (dow < 0) dow += 7;
        int tod = te[1] % TT; if (tod < 0) tod += TT;
        // one_hot(dow,7) ++ one_hot(tod,288) @ W1  ==  W1[dow] + W1[7+tod]
        float v = W1[dow * DD + tid] + W1[(7 + tod) * DD + tid] + b1[tid];
        h[tid] = v > 0.f ? v : 0.f;
    }
    __syncthreads();

    if (tid < DD) {
        float acc = b2[tid];
        #pragma unroll
        for (int d = 0; d < DD; ++d)
            acc = fmaf(h[d], W2[d * DD + tid], acc);   // coalesced W2 columns
        o[tid] = acc;
    }
    __syncthreads();

    // (tid + k*256) % 16 == tid % 16 -> each thread's source float4 is fixed.
    const float4 v4 = reinterpret_cast<const float4*>(o)[tid & 15];
    float4* __restrict__ base =
        reinterpret_cast<float4*>(out) + (size_t)bt * NV + tid;

    // 3312 stores / 256 threads: 12 full rounds + 240-thread remainder,
    // fully unrolled -> 13 back-to-back STG.128 per thread.
    #pragma unroll
    for (int k = 0; k < 12; ++k)
        base[(size_t)k * 256] = v4;
    if (tid < REM4)
        base[(size_t)12 * 256] = v4;
}

extern "C" void kernel_launch(void* const* d_in, const int* in_sizes, int n_in,
                              void* d_out, int out_size)
{
    const int*   TE = (const int*)  d_in[0];
    const float* W1 = (const float*)d_in[1];
    const float* b1 = (const float*)d_in[2];
    const float* W2 = (const float*)d_in[3];
    const float* b2 = (const float*)d_in[4];
    float* out = (float*)d_out;

    tememb_kernel<<<NBT, 256>>>(TE, W1, b1, W2, b2, out);
}